// round 3
// baseline (speedup 1.0000x reference)
#include <cuda_runtime.h>

#define Bn   4096
#define Tn   64
#define DIN  300
#define Hn   3

// Scratch: xb in [T][H][B] layout so k_rnn loads are fully coalesced.
__device__ float g_xb[Tn * Hn * Bn];   // 3 MB

// lengths may arrive as int32 or int64 depending on the reference's JAX x64
// config. Values are in [1,64] (positive, small) so for int64 the high word
// of element 0 — i.e. ((int*)L)[1] — is 0, while for int32 it is lengths[1]
// which is >= 1. Deterministic detection.
__device__ __forceinline__ int length_at(const void* L, int b, int is64) {
    if (is64) return (int)((const long long*)L)[b];
    return ((const int*)L)[b];
}

__device__ __forceinline__ int detect_is64(const void* L) {
    return ((const int*)L)[1] == 0;
}

// Phase 1: xb[t][h][b] = x[b,t,:] . W_ih[h,:] + b_ih[h] + b_hh[h]
// One warp per (b,t) row; skip rows with t >= len (never read from HBM).
__global__ __launch_bounds__(256) void k_proj(
    const float* __restrict__ x,
    const void*  __restrict__ L,
    const float* __restrict__ W_ih,
    const float* __restrict__ b_ih,
    const float* __restrict__ b_hh)
{
    __shared__ float sW[Hn * DIN];   // 3.6 KB
    for (int i = threadIdx.x; i < Hn * DIN; i += blockDim.x) sW[i] = W_ih[i];
    __syncthreads();

    const int warp = (blockIdx.x * blockDim.x + threadIdx.x) >> 5;
    const int lane = threadIdx.x & 31;
    if (warp >= Bn * Tn) return;
    const int b = warp / Tn;
    const int t = warp % Tn;

    const int is64 = detect_is64(L);
    const int len  = length_at(L, b, is64);
    if (t >= len) return;   // dead row: contribute no HBM traffic

    const float* __restrict__ xr = x + (size_t)(b * Tn + t) * DIN;
    float a0 = 0.f, a1 = 0.f, a2 = 0.f;
    #pragma unroll
    for (int i = lane; i < DIN; i += 32) {
        const float v = xr[i];
        a0 += v * sW[i];
        a1 += v * sW[DIN + i];
        a2 += v * sW[2 * DIN + i];
    }
    #pragma unroll
    for (int off = 16; off; off >>= 1) {
        a0 += __shfl_xor_sync(0xffffffffu, a0, off);
        a1 += __shfl_xor_sync(0xffffffffu, a1, off);
        a2 += __shfl_xor_sync(0xffffffffu, a2, off);
    }
    if (lane < Hn) {
        const float a = (lane == 0) ? a0 : (lane == 1 ? a1 : a2);
        g_xb[(t * Hn + lane) * Bn + b] = a + b_ih[lane] + b_hh[lane];
    }
}

// Phase 2: per-sample sequential recurrence. One thread per sample,
// 32-thread blocks so the 128 blocks spread across SMs. xb is L2-resident;
// 2-deep software prefetch hides L2 latency behind the FMA+tanh chain.
__global__ __launch_bounds__(32) void k_rnn(
    const void*  __restrict__ L,
    const float* __restrict__ W_hh,
    float*       __restrict__ out)
{
    const int b = blockIdx.x * 32 + threadIdx.x;
    if (b >= Bn) return;
    const int is64 = detect_is64(L);
    const int len  = length_at(L, b, is64);   // guaranteed >= 1

    const float w00 = W_hh[0], w01 = W_hh[1], w02 = W_hh[2];
    const float w10 = W_hh[3], w11 = W_hh[4], w12 = W_hh[5];
    const float w20 = W_hh[6], w21 = W_hh[7], w22 = W_hh[8];

    const float* __restrict__ p = g_xb + b;   // stride 3*Bn per timestep, Bn per component
    float h0 = 0.f, h1 = 0.f, h2 = 0.f;

    // prefetch pipeline: c = values for step t, n = values for step t+1
    float c0 = p[0], c1 = p[Bn], c2 = p[2 * Bn];
    {
        const int t1 = (1 < len) ? 1 : 0;
        const float* q = p + (size_t)t1 * 3 * Bn;
        // note: loads below overwrite n* in-loop; init here
        c0 = p[0]; c1 = p[Bn]; c2 = p[2 * Bn];
        float dummy = 0.f; (void)dummy; (void)q;
    }
    float n0, n1, n2;
    {
        const int t1 = (1 < len) ? 1 : 0;
        const float* q = p + (size_t)t1 * 3 * Bn;
        n0 = q[0]; n1 = q[Bn]; n2 = q[2 * Bn];
    }

    for (int t = 0; t < len; ++t) {
        const float x0 = c0, x1 = c1, x2 = c2;
        c0 = n0; c1 = n1; c2 = n2;
        const int t2 = (t + 2 < len) ? (t + 2) : (len - 1);
        const float* q = p + (size_t)t2 * 3 * Bn;
        n0 = q[0]; n1 = q[Bn]; n2 = q[2 * Bn];

        const float a0 = x0 + h0 * w00 + h1 * w01 + h2 * w02;
        const float a1 = x1 + h0 * w10 + h1 * w11 + h2 * w12;
        const float a2 = x2 + h0 * w20 + h1 * w21 + h2 * w22;
        h0 = tanhf(a0);
        h1 = tanhf(a1);
        h2 = tanhf(a2);
    }

    out[b * Hn + 0] = h0;
    out[b * Hn + 1] = h1;
    out[b * Hn + 2] = h2;
}

extern "C" void kernel_launch(void* const* d_in, const int* in_sizes, int n_in,
                              void* d_out, int out_size)
{
    const float* x    = (const float*)d_in[0];
    const void*  L    = d_in[1];
    const float* W_ih = (const float*)d_in[2];
    const float* W_hh = (const float*)d_in[3];
    const float* b_ih = (const float*)d_in[4];
    const float* b_hh = (const float*)d_in[5];
    float* out = (float*)d_out;

    const int rows   = Bn * Tn;          // 262144 warps, one per (b,t)
    const int blocks = rows / 8;         // 8 warps (256 threads) per block

    k_proj<<<blocks, 256>>>(x, L, W_ih, b_ih, b_hh);
    k_rnn<<<Bn / 32, 32>>>(L, W_hh, out);
}

// round 5
// speedup vs baseline: 1.3002x; 1.3002x over previous
#include <cuda_runtime.h>

#define Bn   4096
#define Tn   64
#define DIN  300
#define Hn   3
#define DIN4 75   // 300/4

// xb in padded [t][b][4] layout: one aligned float4 per (t,b) for k_rnn.
__device__ float g_xb[(size_t)Tn * Bn * 4];   // 4 MB

// lengths may arrive as int32 or int64. Values are in [1,64] so for int64 the
// high word of element 0 — ((int*)L)[1] — is 0, while for int32 it is
// lengths[1] >= 1. Deterministic detection.
__device__ __forceinline__ int detect_is64(const void* L) {
    return ((const int*)L)[1] == 0;
}
__device__ __forceinline__ int length_at(const void* L, int b, int is64) {
    if (is64) return (int)((const long long*)L)[b];
    return ((const int*)L)[b];
}

// fast accurate tanh: 1 - 2/(e^{2x}+1). MUFU EX2 + RCP, ~few ulp, saturates
// correctly (e^{2x}=inf -> 1, e^{2x}=0 -> -1). No branches.
__device__ __forceinline__ float fast_tanh(float x) {
    float e = __expf(2.0f * x);
    return 1.0f - __fdividef(2.0f, e + 1.0f);
}

// ---------------------------------------------------------------------------
// Phase 1: xb[t][b][.] = x[b,t,:] . W_ih[h,:] + b_ih[h] + b_hh[h], h=0..2
// One warp handles 8 consecutive timesteps of one sample. Weights live in
// 36 registers per lane (float4 slices), so the inner loop does ONLY x loads
// (LDG.128) + FMAs — no shared-memory traffic competing for L1tex wavefronts.
// Output written as a single lane-0 float4 store per row (full-sector).
// ---------------------------------------------------------------------------
__global__ __launch_bounds__(256) void k_proj(
    const float* __restrict__ x,
    const void*  __restrict__ L,
    const float* __restrict__ W_ih,
    const float* __restrict__ b_ih,
    const float* __restrict__ b_hh)
{
    const int gw   = (blockIdx.x * blockDim.x + threadIdx.x) >> 5;  // warp id
    const int lane = threadIdx.x & 31;
    const int b     = gw >> 3;          // sample
    const int tbase = (gw & 7) << 3;    // first of 8 timesteps

    const int is64 = detect_is64(L);
    const int len  = length_at(L, b, is64);
    if (tbase >= len) return;           // whole row-group dead: zero HBM traffic

    // per-lane register weight slices: w[h][k] covers cols 4*(lane+32k)..+3
    const float4* __restrict__ W4 = (const float4*)W_ih;
    float4 w[Hn][3];
    #pragma unroll
    for (int h = 0; h < Hn; ++h)
        #pragma unroll
        for (int k = 0; k < 3; ++k) {
            const int j = lane + 32 * k;
            w[h][k] = (j < DIN4) ? W4[h * DIN4 + j] : make_float4(0.f, 0.f, 0.f, 0.f);
        }

    const float bs0 = b_ih[0] + b_hh[0];
    const float bs1 = b_ih[1] + b_hh[1];
    const float bs2 = b_ih[2] + b_hh[2];

    const float4* __restrict__ xr = (const float4*)x + (size_t)(b * Tn + tbase) * DIN4;
    const int nrows = (len - tbase < 8) ? (len - tbase) : 8;
    float4* __restrict__ xb4 = (float4*)g_xb;

    for (int r = 0; r < nrows; ++r, xr += DIN4) {
        float a0 = 0.f, a1 = 0.f, a2 = 0.f;
        #pragma unroll
        for (int k = 0; k < 3; ++k) {
            const int j = lane + 32 * k;
            if (j < DIN4) {
                const float4 v = xr[j];
                a0 += v.x * w[0][k].x + v.y * w[0][k].y + v.z * w[0][k].z + v.w * w[0][k].w;
                a1 += v.x * w[1][k].x + v.y * w[1][k].y + v.z * w[1][k].z + v.w * w[1][k].w;
                a2 += v.x * w[2][k].x + v.y * w[2][k].y + v.z * w[2][k].z + v.w * w[2][k].w;
            }
        }
        #pragma unroll
        for (int off = 16; off; off >>= 1) {
            a0 += __shfl_xor_sync(0xffffffffu, a0, off);
            a1 += __shfl_xor_sync(0xffffffffu, a1, off);
            a2 += __shfl_xor_sync(0xffffffffu, a2, off);
        }
        // fully-reduced values live on every lane; lane 0 does one 16B store
        if (lane == 0) {
            float4 o;
            o.x = a0 + bs0;
            o.y = a1 + bs1;
            o.z = a2 + bs2;
            o.w = 0.f;
            xb4[(size_t)(tbase + r) * Bn + b] = o;
        }
    }
}

// ---------------------------------------------------------------------------
// Phase 2: sequential recurrence, one thread per sample. One float4 load per
// step (coalesced 512B/warp, L2-resident), 4-deep rolling prefetch, MUFU-based
// tanh. Step chain ~60 cycles -> ~2-3 us total.
// ---------------------------------------------------------------------------
__global__ __launch_bounds__(32) void k_rnn(
    const void*  __restrict__ L,
    const float* __restrict__ W_hh,
    float*       __restrict__ out)
{
    const int b = blockIdx.x * 32 + threadIdx.x;
    if (b >= Bn) return;
    const int is64 = detect_is64(L);
    const int len  = length_at(L, b, is64);   // >= 1

    const float w00 = W_hh[0], w01 = W_hh[1], w02 = W_hh[2];
    const float w10 = W_hh[3], w11 = W_hh[4], w12 = W_hh[5];
    const float w20 = W_hh[6], w21 = W_hh[7], w22 = W_hh[8];

    const float4* __restrict__ p = (const float4*)g_xb;   // [t][b]

    // 4-deep prefetch pipeline (clamped to len-1; len >= 1 so safe)
    const int lm1 = len - 1;
    float4 f0 = p[(size_t)0 * Bn + b];
    float4 f1 = p[(size_t)((1 < lm1) ? 1 : lm1) * Bn + b];
    float4 f2 = p[(size_t)((2 < lm1) ? 2 : lm1) * Bn + b];
    float4 f3 = p[(size_t)((3 < lm1) ? 3 : lm1) * Bn + b];

    float h0 = 0.f, h1 = 0.f, h2 = 0.f;

    for (int t = 0; t < len; ++t) {
        const float x0 = f0.x, x1 = f0.y, x2 = f0.z;
        f0 = f1; f1 = f2; f2 = f3;
        const int tn = (t + 4 < lm1) ? (t + 4) : lm1;
        f3 = p[(size_t)tn * Bn + b];

        const float a0 = x0 + h0 * w00 + h1 * w01 + h2 * w02;
        const float a1 = x1 + h0 * w10 + h1 * w11 + h2 * w12;
        const float a2 = x2 + h0 * w20 + h1 * w21 + h2 * w22;
        h0 = fast_tanh(a0);
        h1 = fast_tanh(a1);
        h2 = fast_tanh(a2);
    }

    out[b * Hn + 0] = h0;
    out[b * Hn + 1] = h1;
    out[b * Hn + 2] = h2;
}

extern "C" void kernel_launch(void* const* d_in, const int* in_sizes, int n_in,
                              void* d_out, int out_size)
{
    const float* x    = (const float*)d_in[0];
    const void*  L    = d_in[1];
    const float* W_ih = (const float*)d_in[2];
    const float* W_hh = (const float*)d_in[3];
    const float* b_ih = (const float*)d_in[4];
    const float* b_hh = (const float*)d_in[5];
    float* out = (float*)d_out;

    // 32768 warps (8 timesteps each), 8 warps per block -> 4096 blocks
    k_proj<<<4096, 256>>>(x, L, W_ih, b_ih, b_hh);
    k_rnn<<<Bn / 32, 32>>>(L, W_hh, out);
}